// round 13
// baseline (speedup 1.0000x reference)
#include <cuda_runtime.h>
#include <cuda_bf16.h>

#define FULLMASK 0xffffffffu
#define WPB 8
#define NTH (WPB * 32)

#define RADIUS_ 0.1f
#define TH_ 5e-5f
#define BMIN_ -0.15f
#define BMAX_ 0.15f
#define BIGT_ 1e10f

__device__ int g_ray_counter;

struct Shm {
    float buf[WPB][8][64];     // per-warp broadcast buffer (h1 / u), 16B-aligned
    float2 W2p[64][32];        // W2p[i][j] = (W2[i][j], W2[i][j+32])
    float2 W2q[64][32];        // W2q[j][i] = (W2[i][j], W2[i+32][j])
    float W1[3][64];
    float b1[64], b2[64], W3[64];
    float b3;
};

__device__ __forceinline__ float sp_(float x) {
    return fmaxf(x, 0.f) + __logf(1.f + __expf(-fabsf(x)));
}
__device__ __forceinline__ float sig_(float x) {
    return 1.f / (1.f + __expf(-x));
}
__device__ __forceinline__ float wsum(float v) {
    v += __shfl_xor_sync(FULLMASK, v, 16);
    v += __shfl_xor_sync(FULLMASK, v, 8);
    v += __shfl_xor_sync(FULLMASK, v, 4);
    v += __shfl_xor_sync(FULLMASK, v, 2);
    v += __shfl_xor_sync(FULLMASK, v, 1);
    return v;
}

// Warp-cooperative SDF eval of B points p = o + t[b]*d. All lanes get all B results.
template <int B>
__device__ __forceinline__ void sdf_eval(Shm& s, int w,
                                         float ox, float oy, float oz,
                                         float dx, float dy, float dz,
                                         const float* t, float* outv) {
    const int lane = threadIdx.x & 31;
    const int lane2 = lane + 32;
    float r[B];
    __syncwarp();
#pragma unroll
    for (int b = 0; b < B; b++) {
        float px = fmaf(t[b], dx, ox);
        float py = fmaf(t[b], dy, oy);
        float pz = fmaf(t[b], dz, oz);
        r[b] = sqrtf(fmaf(px, px, fmaf(py, py, pz * pz)) + 1e-12f);
        float za = fmaf(pz, s.W1[2][lane],
                   fmaf(py, s.W1[1][lane], fmaf(px, s.W1[0][lane], s.b1[lane])));
        float zb = fmaf(pz, s.W1[2][lane2],
                   fmaf(py, s.W1[1][lane2], fmaf(px, s.W1[0][lane2], s.b1[lane2])));
        s.buf[w][b][lane] = sp_(za);
        s.buf[w][b][lane2] = sp_(zb);
    }
    __syncwarp();
    float za[B], zb[B];
#pragma unroll
    for (int b = 0; b < B; b++) { za[b] = s.b2[lane]; zb[b] = s.b2[lane2]; }
#pragma unroll 2
    for (int i = 0; i < 64; i += 4) {
        float2 w0 = s.W2p[i + 0][lane];
        float2 w1 = s.W2p[i + 1][lane];
        float2 w2 = s.W2p[i + 2][lane];
        float2 w3 = s.W2p[i + 3][lane];
#pragma unroll
        for (int b = 0; b < B; b++) {
            float4 h = *(const float4*)&s.buf[w][b][i];
            za[b] = fmaf(h.x, w0.x, za[b]); zb[b] = fmaf(h.x, w0.y, zb[b]);
            za[b] = fmaf(h.y, w1.x, za[b]); zb[b] = fmaf(h.y, w1.y, zb[b]);
            za[b] = fmaf(h.z, w2.x, za[b]); zb[b] = fmaf(h.z, w2.y, zb[b]);
            za[b] = fmaf(h.w, w3.x, za[b]); zb[b] = fmaf(h.w, w3.y, zb[b]);
        }
    }
    float w3a = s.W3[lane], w3b = s.W3[lane2];
    float b3 = s.b3;
#pragma unroll
    for (int b = 0; b < B; b++) {
        float part = fmaf(sp_(za[b]), w3a, sp_(zb[b]) * w3b);
        float z3 = wsum(part) + b3;
        float pert = tanhf(z3);
        outv[b] = r[b] - RADIUS_ + 0.01f * pert;
    }
}

// Analytic gradient of the SDF, normalized. All lanes get the normal.
__device__ __forceinline__ void sdf_normal(Shm& s, int w,
                                           float px, float py, float pz, float* nrm) {
    const int lane = threadIdx.x & 31;
    const int lane2 = lane + 32;
    float za = fmaf(pz, s.W1[2][lane],
               fmaf(py, s.W1[1][lane], fmaf(px, s.W1[0][lane], s.b1[lane])));
    float zb = fmaf(pz, s.W1[2][lane2],
               fmaf(py, s.W1[1][lane2], fmaf(px, s.W1[0][lane2], s.b1[lane2])));
    float s1a = sig_(za), s1b = sig_(zb);
    __syncwarp();
    s.buf[w][0][lane] = sp_(za);
    s.buf[w][0][lane2] = sp_(zb);
    __syncwarp();
    float z2a = s.b2[lane], z2b = s.b2[lane2];
#pragma unroll 2
    for (int i = 0; i < 64; i += 4) {
        float2 w0 = s.W2p[i + 0][lane];
        float2 w1 = s.W2p[i + 1][lane];
        float2 w2 = s.W2p[i + 2][lane];
        float2 w3 = s.W2p[i + 3][lane];
        float4 h = *(const float4*)&s.buf[w][0][i];
        z2a = fmaf(h.x, w0.x, z2a); z2b = fmaf(h.x, w0.y, z2b);
        z2a = fmaf(h.y, w1.x, z2a); z2b = fmaf(h.y, w1.y, z2b);
        z2a = fmaf(h.z, w2.x, z2a); z2b = fmaf(h.z, w2.y, z2b);
        z2a = fmaf(h.w, w3.x, z2a); z2b = fmaf(h.w, w3.y, z2b);
    }
    float w3a = s.W3[lane], w3b = s.W3[lane2];
    float part = fmaf(sp_(z2a), w3a, sp_(z2b) * w3b);
    float z3 = wsum(part) + s.b3;
    float t = tanhf(z3);
    float ua = w3a * sig_(z2a), ub = w3b * sig_(z2b);
    __syncwarp();
    s.buf[w][0][lane] = ua;
    s.buf[w][0][lane2] = ub;
    __syncwarp();
    float sa = 0.f, sb = 0.f;
#pragma unroll 2
    for (int j = 0; j < 64; j += 4) {
        float2 q0 = s.W2q[j + 0][lane];
        float2 q1 = s.W2q[j + 1][lane];
        float2 q2 = s.W2q[j + 2][lane];
        float2 q3 = s.W2q[j + 3][lane];
        float4 u = *(const float4*)&s.buf[w][0][j];
        sa = fmaf(u.x, q0.x, sa); sb = fmaf(u.x, q0.y, sb);
        sa = fmaf(u.y, q1.x, sa); sb = fmaf(u.y, q1.y, sb);
        sa = fmaf(u.z, q2.x, sa); sb = fmaf(u.z, q2.y, sb);
        sa = fmaf(u.w, q3.x, sa); sb = fmaf(u.w, q3.y, sb);
    }
    float g1a = s1a * sa, g1b = s1b * sb;
    float gx = wsum(fmaf(s.W1[0][lane], g1a, s.W1[0][lane2] * g1b));
    float gy = wsum(fmaf(s.W1[1][lane], g1a, s.W1[1][lane2] * g1b));
    float gz = wsum(fmaf(s.W1[2][lane], g1a, s.W1[2][lane2] * g1b));
    float coef = 0.01f * (1.f - t * t);
    float r = sqrtf(fmaf(px, px, fmaf(py, py, pz * pz)) + 1e-12f);
    float invr = 1.f / r;
    float Gx = fmaf(coef, gx, px * invr);
    float Gy = fmaf(coef, gy, py * invr);
    float Gz = fmaf(coef, gz, pz * invr);
    float nn = sqrtf(Gx * Gx + Gy * Gy + Gz * Gz) + 1e-12f;
    float inv = 1.f / nn;
    nrm[0] = Gx * inv; nrm[1] = Gy * inv; nrm[2] = Gz * inv;
}

__device__ __forceinline__ void aabb(float ox, float oy, float oz,
                                     float dx, float dy, float dz,
                                     float& t_near, float& t_far, bool& hit) {
    float ddx = (fabsf(dx) < 1e-9f) ? 1e-9f : dx;
    float ddy = (fabsf(dy) < 1e-9f) ? 1e-9f : dy;
    float ddz = (fabsf(dz) < 1e-9f) ? 1e-9f : dz;
    float ix = 1.f / ddx, iy = 1.f / ddy, iz = 1.f / ddz;
    float t1x = (BMIN_ - ox) * ix, t2x = (BMAX_ - ox) * ix;
    float t1y = (BMIN_ - oy) * iy, t2y = (BMAX_ - oy) * iy;
    float t1z = (BMIN_ - oz) * iz, t2z = (BMAX_ - oz) * iz;
    float tmin = fmaxf(fmaxf(fminf(t1x, t2x), fminf(t1y, t2y)), fminf(t1z, t2z));
    float tmax = fminf(fminf(fmaxf(t1x, t2x), fmaxf(t1y, t2y)), fmaxf(t1z, t2z));
    hit = (tmax >= tmin) && (tmax > 0.f);
    t_near = hit ? fmaxf(tmin, 0.f) : BIGT_;
    t_far = hit ? tmax : BIGT_;
}

__device__ __forceinline__ void refract(float lx, float ly, float lz,
                                        float nx, float ny, float nz,
                                        float eta1, float eta2,
                                        float* t, float& att) {
    float ct = -(lx * nx + ly * ny + lz * nz);
    float ipx = fmaf(nx, ct, lx);
    float ipy = fmaf(ny, ct, ly);
    float ipz = fmaf(nz, ct, lz);
    float k = eta1 / eta2;
    float tpx = k * ipx, tpy = k * ipy, tpz = k * ipz;
    float tpn = tpx * tpx + tpy * tpy + tpz * tpz;
    float c = fminf(fmaxf(tpn, 0.f), 0.999999f);
    float ti = sqrtf(1.f - c);
    float tx = fmaf(-nx, ti, tpx);
    float ty = fmaf(-ny, ti, tpy);
    float tz = fmaf(-nz, ti, tpz);
    float nn = sqrtf(tx * tx + ty * ty + tz * tz) + 1e-10f;
    float inv = 1.f / nn;
    tx *= inv; ty *= inv; tz *= inv;
    float ctt = -(tx * nx + ty * ny + tz * nz);
    float ei = (ctt * eta1 - ct * eta2) / (ctt * eta1 + ct * eta2 + 1e-10f);
    float ep = (ctt * eta2 - ct * eta1) / (ctt * eta2 + ct * eta1 + 1e-10f);
    att = fminf(fmaxf(0.5f * (ei * ei + ep * ep), 0.f), 1.f);
    t[0] = tx; t[1] = ty; t[2] = tz;
}

__device__ __forceinline__ void reflect(float lx, float ly, float lz,
                                        const float* n, float* r) {
    float dn = lx * n[0] + ly * n[1] + lz * n[2];
    float rx = fmaf(-2.f * dn, n[0], lx);
    float ry = fmaf(-2.f * dn, n[1], ly);
    float rz = fmaf(-2.f * dn, n[2], lz);
    float nn = sqrtf(rx * rx + ry * ry + rz * rz) + 1e-10f;
    float inv = 1.f / nn;
    r[0] = rx * inv; r[1] = ry * inv; r[2] = rz * inv;
}

__device__ __forceinline__ void intersect_sdf(Shm& s, int w,
                                              float ox, float oy, float oz,
                                              float dx, float dy, float dz,
                                              bool mask, float t_near, float t_far, bool far_,
                                              bool& valid, float& depth, float* nrm) {
    float acc_s = mask ? t_near : 0.f;
    float acc_e = mask ? t_far : 0.f;
    bool unf_s = false, unf_e = false;
    if (mask) {
        float t[2] = {acc_s, acc_e};
        float v[2];
        sdf_eval<2>(s, w, ox, oy, oz, dx, dy, dz, t, v);
        unf_s = fabsf(v[0]) > TH_;
        unf_e = fabsf(v[1]) > TH_;
    }
#pragma unroll 1
    for (int it = 0; it < 15; ++it) {
        if (!(unf_s || unf_e)) break;
        float cs = 0.f, ce = 0.f;
        if (unf_s && unf_e) {
            float t[2] = {acc_s, acc_e};
            float v[2];
            sdf_eval<2>(s, w, ox, oy, oz, dx, dy, dz, t, v);
            cs = v[0]; ce = v[1];
        } else if (unf_s) {
            sdf_eval<1>(s, w, ox, oy, oz, dx, dy, dz, &acc_s, &cs);
        } else {
            sdf_eval<1>(s, w, ox, oy, oz, dx, dy, dz, &acc_e, &ce);
        }
        if (unf_s) acc_s += cs;
        if (unf_e) acc_e -= ce;
        bool nc = acc_s < acc_e;
        unf_s = unf_s && (fabsf(cs) > TH_) && nc;
        unf_e = unf_e && (fabsf(ce) > TH_) && nc;
    }
    bool net = acc_s < acc_e;
    bool smask = far_ ? unf_e : unf_s;
    if (smask) {
        const int lane = threadIdx.x & 31;
        float dt = acc_e - acc_s;
        float vlo = 0.f, vhi = 0.f;
#pragma unroll 1
        for (int base = 0; base < 64; base += 8) {
            float t[8], v[8];
#pragma unroll
            for (int j = 0; j < 8; j++)
                t[j] = fmaf((float)(base + j) * (1.f / 63.f), dt, acc_s);
            sdf_eval<8>(s, w, ox, oy, oz, dx, dy, dz, t, v);
#pragma unroll
            for (int j = 0; j < 8; j++) {
                int k = base + j;
                if (lane == k) vlo = v[j];
                if (lane == k - 32) vhi = v[j];
            }
        }
        unsigned mlo = __ballot_sync(FULLMASK, vlo < 0.f);
        unsigned mhi = __ballot_sync(FULLMASK, vhi < 0.f);
        unsigned long long m = (((unsigned long long)mhi) << 32) | (unsigned long long)mlo;
        bool any = (m != 0ull);
        int ia, ib;
        bool has;
        if (!far_) {
            int idx = any ? (__ffsll((long long)m) - 1) : 0;
            has = any && (idx > 0);
            ia = (idx > 0) ? idx - 1 : 0;
            ib = idx;
        } else {
            int ln = any ? (63 - __clzll((long long)m)) : 63;
            has = any && (ln < 63);
            ia = ln;
            ib = (ln + 1 > 63) ? 63 : ln + 1;
        }
        float f_a = (ia < 32) ? __shfl_sync(FULLMASK, vlo, ia) : __shfl_sync(FULLMASK, vhi, ia - 32);
        float f_b = (ib < 32) ? __shfl_sync(FULLMASK, vlo, ib) : __shfl_sync(FULLMASK, vhi, ib - 32);
        float t_a = fmaf((float)ia * (1.f / 63.f), dt, acc_s);
        float t_b = fmaf((float)ib * (1.f / 63.f), dt, acc_s);
#pragma unroll 1
        for (int it = 0; it < 8; ++it) {
            float den = f_b - f_a;
            if (fabsf(den) < 1e-12f) den = 1e-12f;
            float t_mid = t_a - f_a * (t_b - t_a) / den;
            float fm;
            sdf_eval<1>(s, w, ox, oy, oz, dx, dy, dz, &t_mid, &fm);
            bool same = (fm > 0.f) == (f_a > 0.f);
            if (same) { t_a = t_mid; f_a = fm; }
            else      { t_b = t_mid; f_b = fm; }
        }
        float den = f_b - f_a;
        if (fabsf(den) < 1e-12f) den = 1e-12f;
        depth = t_a - f_a * (t_b - t_a) / den;
        net = has;
    } else {
        depth = far_ ? acc_e : acc_s;
    }
    valid = net && mask;
    nrm[0] = 0.f; nrm[1] = 0.f; nrm[2] = 0.f;
    if (valid) {
        sdf_normal(s, w, fmaf(depth, dx, ox), fmaf(depth, dy, oy), fmaf(depth, dz, oz), nrm);
    }
}

__device__ __forceinline__ void process_ray(Shm& s, int w, int ray,
                                            const float* __restrict__ go,
                                            const float* __restrict__ gd,
                                            float* __restrict__ out, int N) {
    int tid = threadIdx.x;
    float ox = go[ray * 3 + 0], oy = go[ray * 3 + 1], oz = go[ray * 3 + 2];
    float dx = gd[ray * 3 + 0], dy = gd[ray * 3 + 1], dz = gd[ray * 3 + 2];

    float tn, tf;
    bool hit;
    aabb(ox, oy, oz, dx, dy, dz, tn, tf, hit);

    bool valid;
    float depth1;
    float n1[3];
    intersect_sdf(s, w, ox, oy, oz, dx, dy, dz, hit, tn, tf, false, valid, depth1, n1);

    float fpx = fmaf(depth1, dx, ox);
    float fpy = fmaf(depth1, dy, oy);
    float fpz = fmaf(depth1, dz, oz);
    bool inside = (fpx >= BMIN_) && (fpx <= BMAX_) &&
                  (fpy >= BMIN_) && (fpy <= BMAX_) &&
                  (fpz >= BMIN_) && (fpz <= BMAX_);

    float lt1[3], att1;
    refract(dx, dy, dz, n1[0], n1[1], n1[2], 1.0003f, 1.45f, lt1, att1);
    float lr1[3];
    reflect(dx, dy, dz, n1, lr1);

    float o2x = fpx - lt1[0], o2y = fpy - lt1[1], o2z = fpz - lt1[2];
    float d2x = lt1[0], d2y = lt1[1], d2z = lt1[2];

    float tn2, tf2;
    bool hit2;
    aabb(o2x, o2y, o2z, d2x, d2y, d2z, tn2, tf2, hit2);
    bool mask2 = hit2 && inside && valid;

    bool valid2;
    float depth2;
    float n2[3];
    intersect_sdf(s, w, o2x, o2y, o2z, d2x, d2y, d2z, mask2, tn2, tf2, true, valid2, depth2, n2);

    float spx = fmaf(depth2, d2x, o2x);
    float spy = fmaf(depth2, d2y, o2y);
    float spz = fmaf(depth2, d2z, o2z);

    float lt2[3], att2_unused;
    refract(d2x, d2y, d2z, -n2[0], -n2[1], -n2[2], 1.45f, 1.0003f, lt2, att2_unused);

    bool fin = valid && valid2;

    if ((tid & 31) == 0) {
        float* out_o = out;
        float* out_d = out + 3 * N;
        float* refl_o = out + 6 * N;
        float* refl_d = out + 9 * N;
        float* att_o = out + 12 * N;
        float* fin_o = out + 13 * N;
        float* fp_o = out + 14 * N;
        float* sp_o = out + 17 * N;

        if (fin) {
            out_o[ray * 3 + 0] = fmaf(0.1f, lt2[0], spx);
            out_o[ray * 3 + 1] = fmaf(0.1f, lt2[1], spy);
            out_o[ray * 3 + 2] = fmaf(0.1f, lt2[2], spz);
            out_d[ray * 3 + 0] = lt2[0];
            out_d[ray * 3 + 1] = lt2[1];
            out_d[ray * 3 + 2] = lt2[2];
            refl_o[ray * 3 + 0] = fmaf(0.1f, lr1[0], fpx);
            refl_o[ray * 3 + 1] = fmaf(0.1f, lr1[1], fpy);
            refl_o[ray * 3 + 2] = fmaf(0.1f, lr1[2], fpz);
            refl_d[ray * 3 + 0] = lr1[0];
            refl_d[ray * 3 + 1] = lr1[1];
            refl_d[ray * 3 + 2] = lr1[2];
        } else {
            out_o[ray * 3 + 0] = ox; out_o[ray * 3 + 1] = oy; out_o[ray * 3 + 2] = oz;
            out_d[ray * 3 + 0] = dx; out_d[ray * 3 + 1] = dy; out_d[ray * 3 + 2] = dz;
            refl_o[ray * 3 + 0] = ox; refl_o[ray * 3 + 1] = oy; refl_o[ray * 3 + 2] = oz;
            refl_d[ray * 3 + 0] = dx; refl_d[ray * 3 + 1] = dy; refl_d[ray * 3 + 2] = dz;
        }
        att_o[ray] = fin ? att1 : 0.f;
        fin_o[ray] = fin ? 1.f : 0.f;
        fp_o[ray * 3 + 0] = fpx; fp_o[ray * 3 + 1] = fpy; fp_o[ray * 3 + 2] = fpz;
        sp_o[ray * 3 + 0] = spx; sp_o[ray * 3 + 1] = spy; sp_o[ray * 3 + 2] = spz;
    }
}

__global__ void zero_counter_kernel() {
    g_ray_counter = 0;
}

__global__ void __launch_bounds__(NTH, 3)
trace_kernel(const float* __restrict__ go, const float* __restrict__ gd,
             const float* __restrict__ gW1, const float* __restrict__ gb1,
             const float* __restrict__ gW2, const float* __restrict__ gb2,
             const float* __restrict__ gW3, const float* __restrict__ gb3,
             float* __restrict__ out, int N) {
    __shared__ __align__(16) Shm s;
    int tid = threadIdx.x;
    for (int i = tid; i < 192; i += NTH) ((float*)s.W1)[i] = gW1[i];
    for (int i = tid; i < 64; i += NTH) {
        s.b1[i] = gb1[i];
        s.b2[i] = gb2[i];
        s.W3[i] = gW3[i];
    }
    if (tid == 0) s.b3 = gb3[0];
    for (int i = tid; i < 64 * 32; i += NTH) {
        int r = i >> 5, c = i & 31;
        s.W2p[r][c] = make_float2(gW2[r * 64 + c], gW2[r * 64 + c + 32]);
        s.W2q[r][c] = make_float2(gW2[c * 64 + r], gW2[(c + 32) * 64 + r]);
    }
    __syncthreads();

    int w = tid >> 5;
    const int lane = tid & 31;

    // Persistent warp loop with dynamic ray fetch.
    for (;;) {
        int ray = 0;
        if (lane == 0) ray = atomicAdd(&g_ray_counter, 1);
        ray = __shfl_sync(FULLMASK, ray, 0);
        if (ray >= N) break;
        process_ray(s, w, ray, go, gd, out, N);
    }
}

extern "C" void kernel_launch(void* const* d_in, const int* in_sizes, int n_in,
                              void* d_out, int out_size) {
    const float* o = (const float*)d_in[0];
    const float* d = (const float*)d_in[1];
    const float* W1 = (const float*)d_in[2];
    const float* b1 = (const float*)d_in[3];
    const float* W2 = (const float*)d_in[4];
    const float* b2 = (const float*)d_in[5];
    const float* W3 = (const float*)d_in[6];
    const float* b3 = (const float*)d_in[7];
    int N = in_sizes[0] / 3;

    zero_counter_kernel<<<1, 1>>>();

    // Persistent grid: 3 blocks/SM x 148 SMs.
    int blocks = 444;
    int max_blocks = (N + WPB - 1) / WPB;
    if (blocks > max_blocks) blocks = max_blocks;
    trace_kernel<<<blocks, NTH>>>(o, d, W1, b1, W2, b2, W3, b3, (float*)d_out, N);
}

// round 14
// speedup vs baseline: 1.1583x; 1.1583x over previous
#include <cuda_runtime.h>
#include <cuda_bf16.h>

#define FULLMASK 0xffffffffu
#define WPB 8
#define NTH (WPB * 32)

#define RADIUS_ 0.1f
#define TH_ 5e-5f
#define BMIN_ -0.15f
#define BMAX_ 0.15f
#define BIGT_ 1e10f

__device__ int g_ray_counter;

struct Shm {
    float buf[WPB][4][64];     // per-warp broadcast buffer (h1 / u), 16B-aligned
    float2 W2p[64][32];        // W2p[i][j] = (W2[i][j], W2[i][j+32])
    float2 W2q[64][32];        // W2q[j][i] = (W2[i][j], W2[i+32][j])
    float W1[3][64];
    float b1[64], b2[64], W3[64];
    float b3;
};

// Per-lane loop-invariant weights held in registers (hoisted out of sdf_eval).
struct LaneW {
    float w1xa, w1ya, w1za, b1a;
    float w1xb, w1yb, w1zb, b1b;
    float b2a, b2b, w3a, w3b, b3;
};

__device__ __forceinline__ float sp_(float x) {
    return fmaxf(x, 0.f) + __logf(1.f + __expf(-fabsf(x)));
}
__device__ __forceinline__ float sig_(float x) {
    return 1.f / (1.f + __expf(-x));
}
__device__ __forceinline__ float wsum(float v) {
    v += __shfl_xor_sync(FULLMASK, v, 16);
    v += __shfl_xor_sync(FULLMASK, v, 8);
    v += __shfl_xor_sync(FULLMASK, v, 4);
    v += __shfl_xor_sync(FULLMASK, v, 2);
    v += __shfl_xor_sync(FULLMASK, v, 1);
    return v;
}

// Warp-cooperative SDF eval of B points p = o + t[b]*d. All lanes get all B results.
template <int B>
__device__ __forceinline__ void sdf_eval(Shm& s, int w, const LaneW& lw,
                                         float ox, float oy, float oz,
                                         float dx, float dy, float dz,
                                         const float* t, float* outv) {
    const int lane = threadIdx.x & 31;
    float r[B];
    __syncwarp();
#pragma unroll
    for (int b = 0; b < B; b++) {
        float px = fmaf(t[b], dx, ox);
        float py = fmaf(t[b], dy, oy);
        float pz = fmaf(t[b], dz, oz);
        r[b] = sqrtf(fmaf(px, px, fmaf(py, py, pz * pz)) + 1e-12f);
        float za = fmaf(pz, lw.w1za, fmaf(py, lw.w1ya, fmaf(px, lw.w1xa, lw.b1a)));
        float zb = fmaf(pz, lw.w1zb, fmaf(py, lw.w1yb, fmaf(px, lw.w1xb, lw.b1b)));
        s.buf[w][b][lane] = sp_(za);
        s.buf[w][b][lane + 32] = sp_(zb);
    }
    __syncwarp();
    float za[B], zb[B];
#pragma unroll
    for (int b = 0; b < B; b++) { za[b] = lw.b2a; zb[b] = lw.b2b; }
#pragma unroll 2
    for (int i = 0; i < 64; i += 4) {
        float2 w0 = s.W2p[i + 0][lane];
        float2 w1 = s.W2p[i + 1][lane];
        float2 w2 = s.W2p[i + 2][lane];
        float2 w3 = s.W2p[i + 3][lane];
#pragma unroll
        for (int b = 0; b < B; b++) {
            float4 h = *(const float4*)&s.buf[w][b][i];
            za[b] = fmaf(h.x, w0.x, za[b]); zb[b] = fmaf(h.x, w0.y, zb[b]);
            za[b] = fmaf(h.y, w1.x, za[b]); zb[b] = fmaf(h.y, w1.y, zb[b]);
            za[b] = fmaf(h.z, w2.x, za[b]); zb[b] = fmaf(h.z, w2.y, zb[b]);
            za[b] = fmaf(h.w, w3.x, za[b]); zb[b] = fmaf(h.w, w3.y, zb[b]);
        }
    }
#pragma unroll
    for (int b = 0; b < B; b++) {
        float part = fmaf(sp_(za[b]), lw.w3a, sp_(zb[b]) * lw.w3b);
        float z3 = wsum(part) + lw.b3;
        float pert = tanhf(z3);
        outv[b] = r[b] - RADIUS_ + 0.01f * pert;
    }
}

// Analytic gradient of the SDF, normalized. All lanes get the normal.
__device__ __forceinline__ void sdf_normal(Shm& s, int w, const LaneW& lw,
                                           float px, float py, float pz, float* nrm) {
    const int lane = threadIdx.x & 31;
    float za = fmaf(pz, lw.w1za, fmaf(py, lw.w1ya, fmaf(px, lw.w1xa, lw.b1a)));
    float zb = fmaf(pz, lw.w1zb, fmaf(py, lw.w1yb, fmaf(px, lw.w1xb, lw.b1b)));
    float s1a = sig_(za), s1b = sig_(zb);
    __syncwarp();
    s.buf[w][0][lane] = sp_(za);
    s.buf[w][0][lane + 32] = sp_(zb);
    __syncwarp();
    float z2a = lw.b2a, z2b = lw.b2b;
#pragma unroll 2
    for (int i = 0; i < 64; i += 4) {
        float2 w0 = s.W2p[i + 0][lane];
        float2 w1 = s.W2p[i + 1][lane];
        float2 w2 = s.W2p[i + 2][lane];
        float2 w3 = s.W2p[i + 3][lane];
        float4 h = *(const float4*)&s.buf[w][0][i];
        z2a = fmaf(h.x, w0.x, z2a); z2b = fmaf(h.x, w0.y, z2b);
        z2a = fmaf(h.y, w1.x, z2a); z2b = fmaf(h.y, w1.y, z2b);
        z2a = fmaf(h.z, w2.x, z2a); z2b = fmaf(h.z, w2.y, z2b);
        z2a = fmaf(h.w, w3.x, z2a); z2b = fmaf(h.w, w3.y, z2b);
    }
    float part = fmaf(sp_(z2a), lw.w3a, sp_(z2b) * lw.w3b);
    float z3 = wsum(part) + lw.b3;
    float t = tanhf(z3);
    float ua = lw.w3a * sig_(z2a), ub = lw.w3b * sig_(z2b);
    __syncwarp();
    s.buf[w][0][lane] = ua;
    s.buf[w][0][lane + 32] = ub;
    __syncwarp();
    float sa = 0.f, sb = 0.f;
#pragma unroll 2
    for (int j = 0; j < 64; j += 4) {
        float2 q0 = s.W2q[j + 0][lane];
        float2 q1 = s.W2q[j + 1][lane];
        float2 q2 = s.W2q[j + 2][lane];
        float2 q3 = s.W2q[j + 3][lane];
        float4 u = *(const float4*)&s.buf[w][0][j];
        sa = fmaf(u.x, q0.x, sa); sb = fmaf(u.x, q0.y, sb);
        sa = fmaf(u.y, q1.x, sa); sb = fmaf(u.y, q1.y, sb);
        sa = fmaf(u.z, q2.x, sa); sb = fmaf(u.z, q2.y, sb);
        sa = fmaf(u.w, q3.x, sa); sb = fmaf(u.w, q3.y, sb);
    }
    float g1a = s1a * sa, g1b = s1b * sb;
    float gx = wsum(fmaf(lw.w1xa, g1a, lw.w1xb * g1b));
    float gy = wsum(fmaf(lw.w1ya, g1a, lw.w1yb * g1b));
    float gz = wsum(fmaf(lw.w1za, g1a, lw.w1zb * g1b));
    float coef = 0.01f * (1.f - t * t);
    float r = sqrtf(fmaf(px, px, fmaf(py, py, pz * pz)) + 1e-12f);
    float invr = 1.f / r;
    float Gx = fmaf(coef, gx, px * invr);
    float Gy = fmaf(coef, gy, py * invr);
    float Gz = fmaf(coef, gz, pz * invr);
    float nn = sqrtf(Gx * Gx + Gy * Gy + Gz * Gz) + 1e-12f;
    float inv = 1.f / nn;
    nrm[0] = Gx * inv; nrm[1] = Gy * inv; nrm[2] = Gz * inv;
}

__device__ __forceinline__ void aabb(float ox, float oy, float oz,
                                     float dx, float dy, float dz,
                                     float& t_near, float& t_far, bool& hit) {
    float ddx = (fabsf(dx) < 1e-9f) ? 1e-9f : dx;
    float ddy = (fabsf(dy) < 1e-9f) ? 1e-9f : dy;
    float ddz = (fabsf(dz) < 1e-9f) ? 1e-9f : dz;
    float ix = 1.f / ddx, iy = 1.f / ddy, iz = 1.f / ddz;
    float t1x = (BMIN_ - ox) * ix, t2x = (BMAX_ - ox) * ix;
    float t1y = (BMIN_ - oy) * iy, t2y = (BMAX_ - oy) * iy;
    float t1z = (BMIN_ - oz) * iz, t2z = (BMAX_ - oz) * iz;
    float tmin = fmaxf(fmaxf(fminf(t1x, t2x), fminf(t1y, t2y)), fminf(t1z, t2z));
    float tmax = fminf(fminf(fmaxf(t1x, t2x), fmaxf(t1y, t2y)), fmaxf(t1z, t2z));
    hit = (tmax >= tmin) && (tmax > 0.f);
    t_near = hit ? fmaxf(tmin, 0.f) : BIGT_;
    t_far = hit ? tmax : BIGT_;
}

__device__ __forceinline__ void refract(float lx, float ly, float lz,
                                        float nx, float ny, float nz,
                                        float eta1, float eta2,
                                        float* t, float& att) {
    float ct = -(lx * nx + ly * ny + lz * nz);
    float ipx = fmaf(nx, ct, lx);
    float ipy = fmaf(ny, ct, ly);
    float ipz = fmaf(nz, ct, lz);
    float k = eta1 / eta2;
    float tpx = k * ipx, tpy = k * ipy, tpz = k * ipz;
    float tpn = tpx * tpx + tpy * tpy + tpz * tpz;
    float c = fminf(fmaxf(tpn, 0.f), 0.999999f);
    float ti = sqrtf(1.f - c);
    float tx = fmaf(-nx, ti, tpx);
    float ty = fmaf(-ny, ti, tpy);
    float tz = fmaf(-nz, ti, tpz);
    float nn = sqrtf(tx * tx + ty * ty + tz * tz) + 1e-10f;
    float inv = 1.f / nn;
    tx *= inv; ty *= inv; tz *= inv;
    float ctt = -(tx * nx + ty * ny + tz * nz);
    float ei = (ctt * eta1 - ct * eta2) / (ctt * eta1 + ct * eta2 + 1e-10f);
    float ep = (ctt * eta2 - ct * eta1) / (ctt * eta2 + ct * eta1 + 1e-10f);
    att = fminf(fmaxf(0.5f * (ei * ei + ep * ep), 0.f), 1.f);
    t[0] = tx; t[1] = ty; t[2] = tz;
}

__device__ __forceinline__ void reflect(float lx, float ly, float lz,
                                        const float* n, float* r) {
    float dn = lx * n[0] + ly * n[1] + lz * n[2];
    float rx = fmaf(-2.f * dn, n[0], lx);
    float ry = fmaf(-2.f * dn, n[1], ly);
    float rz = fmaf(-2.f * dn, n[2], lz);
    float nn = sqrtf(rx * rx + ry * ry + rz * rz) + 1e-10f;
    float inv = 1.f / nn;
    r[0] = rx * inv; r[1] = ry * inv; r[2] = rz * inv;
}

__device__ __forceinline__ void intersect_sdf(Shm& s, int w, const LaneW& lw,
                                              float ox, float oy, float oz,
                                              float dx, float dy, float dz,
                                              bool mask, float t_near, float t_far, bool far_,
                                              bool& valid, float& depth, float* nrm) {
    float acc_s = mask ? t_near : 0.f;
    float acc_e = mask ? t_far : 0.f;
    bool unf_s = false, unf_e = false;
    float cs = 0.f, ce = 0.f;   // invariant: cs = sdf(acc_s), ce = sdf(acc_e) when flag alive
    if (mask) {
        float t[2] = {acc_s, acc_e};
        float v[2];
        sdf_eval<2>(s, w, lw, ox, oy, oz, dx, dy, dz, t, v);
        cs = v[0]; ce = v[1];
        unf_s = fabsf(cs) > TH_;
        unf_e = fabsf(ce) > TH_;
    }
#pragma unroll 1
    for (int it = 0; it < 15; ++it) {
        if (!(unf_s || unf_e)) break;
        // cs/ce already hold sdf at current acc_s/acc_e (reference evaluates here).
        if (unf_s) acc_s += cs;
        if (unf_e) acc_e -= ce;
        bool nc = acc_s < acc_e;
        unf_s = unf_s && (fabsf(cs) > TH_) && nc;
        unf_e = unf_e && (fabsf(ce) > TH_) && nc;
        if ((unf_s || unf_e) && it < 14) {
            // evaluate at the new positions for the next iteration
            if (unf_s && unf_e) {
                float t[2] = {acc_s, acc_e};
                float v[2];
                sdf_eval<2>(s, w, lw, ox, oy, oz, dx, dy, dz, t, v);
                cs = v[0]; ce = v[1];
            } else if (unf_s) {
                sdf_eval<1>(s, w, lw, ox, oy, oz, dx, dy, dz, &acc_s, &cs);
            } else {
                sdf_eval<1>(s, w, lw, ox, oy, oz, dx, dy, dz, &acc_e, &ce);
            }
        }
    }
    bool net = acc_s < acc_e;
    bool smask = far_ ? unf_e : unf_s;
    if (smask) {
        const int lane = threadIdx.x & 31;
        float dt = acc_e - acc_s;
        float vlo = 0.f, vhi = 0.f;
#pragma unroll 1
        for (int base = 0; base < 64; base += 4) {
            float t[4], v[4];
#pragma unroll
            for (int j = 0; j < 4; j++)
                t[j] = fmaf((float)(base + j) * (1.f / 63.f), dt, acc_s);
            sdf_eval<4>(s, w, lw, ox, oy, oz, dx, dy, dz, t, v);
#pragma unroll
            for (int j = 0; j < 4; j++) {
                int k = base + j;
                if (lane == k) vlo = v[j];
                if (lane == k - 32) vhi = v[j];
            }
        }
        unsigned mlo = __ballot_sync(FULLMASK, vlo < 0.f);
        unsigned mhi = __ballot_sync(FULLMASK, vhi < 0.f);
        unsigned long long m = (((unsigned long long)mhi) << 32) | (unsigned long long)mlo;
        bool any = (m != 0ull);
        int ia, ib;
        bool has;
        if (!far_) {
            int idx = any ? (__ffsll((long long)m) - 1) : 0;
            has = any && (idx > 0);
            ia = (idx > 0) ? idx - 1 : 0;
            ib = idx;
        } else {
            int ln = any ? (63 - __clzll((long long)m)) : 63;
            has = any && (ln < 63);
            ia = ln;
            ib = (ln + 1 > 63) ? 63 : ln + 1;
        }
        float f_a = (ia < 32) ? __shfl_sync(FULLMASK, vlo, ia) : __shfl_sync(FULLMASK, vhi, ia - 32);
        float f_b = (ib < 32) ? __shfl_sync(FULLMASK, vlo, ib) : __shfl_sync(FULLMASK, vhi, ib - 32);
        float t_a = fmaf((float)ia * (1.f / 63.f), dt, acc_s);
        float t_b = fmaf((float)ib * (1.f / 63.f), dt, acc_s);
#pragma unroll 1
        for (int it = 0; it < 8; ++it) {
            // Converged bracket: further iterations change depth by < 1e-7.
            if (fabsf(t_b - t_a) < 1e-7f) break;
            float den = f_b - f_a;
            if (fabsf(den) < 1e-12f) den = 1e-12f;
            float t_mid = t_a - f_a * (t_b - t_a) / den;
            float fm;
            sdf_eval<1>(s, w, lw, ox, oy, oz, dx, dy, dz, &t_mid, &fm);
            bool same = (fm > 0.f) == (f_a > 0.f);
            if (same) { t_a = t_mid; f_a = fm; }
            else      { t_b = t_mid; f_b = fm; }
        }
        float den = f_b - f_a;
        if (fabsf(den) < 1e-12f) den = 1e-12f;
        depth = t_a - f_a * (t_b - t_a) / den;
        net = has;
    } else {
        depth = far_ ? acc_e : acc_s;
    }
    valid = net && mask;
    nrm[0] = 0.f; nrm[1] = 0.f; nrm[2] = 0.f;
    if (valid) {
        sdf_normal(s, w, lw, fmaf(depth, dx, ox), fmaf(depth, dy, oy), fmaf(depth, dz, oz), nrm);
    }
}

__device__ __forceinline__ void process_ray(Shm& s, int w, const LaneW& lw, int ray,
                                            const float* __restrict__ go,
                                            const float* __restrict__ gd,
                                            float* __restrict__ out, int N) {
    int tid = threadIdx.x;
    float ox = go[ray * 3 + 0], oy = go[ray * 3 + 1], oz = go[ray * 3 + 2];
    float dx = gd[ray * 3 + 0], dy = gd[ray * 3 + 1], dz = gd[ray * 3 + 2];

    float tn, tf;
    bool hit;
    aabb(ox, oy, oz, dx, dy, dz, tn, tf, hit);

    bool valid;
    float depth1;
    float n1[3];
    intersect_sdf(s, w, lw, ox, oy, oz, dx, dy, dz, hit, tn, tf, false, valid, depth1, n1);

    float fpx = fmaf(depth1, dx, ox);
    float fpy = fmaf(depth1, dy, oy);
    float fpz = fmaf(depth1, dz, oz);
    bool inside = (fpx >= BMIN_) && (fpx <= BMAX_) &&
                  (fpy >= BMIN_) && (fpy <= BMAX_) &&
                  (fpz >= BMIN_) && (fpz <= BMAX_);

    float lt1[3], att1;
    refract(dx, dy, dz, n1[0], n1[1], n1[2], 1.0003f, 1.45f, lt1, att1);
    float lr1[3];
    reflect(dx, dy, dz, n1, lr1);

    float o2x = fpx - lt1[0], o2y = fpy - lt1[1], o2z = fpz - lt1[2];
    float d2x = lt1[0], d2y = lt1[1], d2z = lt1[2];

    float tn2, tf2;
    bool hit2;
    aabb(o2x, o2y, o2z, d2x, d2y, d2z, tn2, tf2, hit2);
    bool mask2 = hit2 && inside && valid;

    bool valid2;
    float depth2;
    float n2[3];
    intersect_sdf(s, w, lw, o2x, o2y, o2z, d2x, d2y, d2z, mask2, tn2, tf2, true, valid2, depth2, n2);

    float spx = fmaf(depth2, d2x, o2x);
    float spy = fmaf(depth2, d2y, o2y);
    float spz = fmaf(depth2, d2z, o2z);

    float lt2[3], att2_unused;
    refract(d2x, d2y, d2z, -n2[0], -n2[1], -n2[2], 1.45f, 1.0003f, lt2, att2_unused);

    bool fin = valid && valid2;

    if ((tid & 31) == 0) {
        float* out_o = out;
        float* out_d = out + 3 * N;
        float* refl_o = out + 6 * N;
        float* refl_d = out + 9 * N;
        float* att_o = out + 12 * N;
        float* fin_o = out + 13 * N;
        float* fp_o = out + 14 * N;
        float* sp_o = out + 17 * N;

        if (fin) {
            out_o[ray * 3 + 0] = fmaf(0.1f, lt2[0], spx);
            out_o[ray * 3 + 1] = fmaf(0.1f, lt2[1], spy);
            out_o[ray * 3 + 2] = fmaf(0.1f, lt2[2], spz);
            out_d[ray * 3 + 0] = lt2[0];
            out_d[ray * 3 + 1] = lt2[1];
            out_d[ray * 3 + 2] = lt2[2];
            refl_o[ray * 3 + 0] = fmaf(0.1f, lr1[0], fpx);
            refl_o[ray * 3 + 1] = fmaf(0.1f, lr1[1], fpy);
            refl_o[ray * 3 + 2] = fmaf(0.1f, lr1[2], fpz);
            refl_d[ray * 3 + 0] = lr1[0];
            refl_d[ray * 3 + 1] = lr1[1];
            refl_d[ray * 3 + 2] = lr1[2];
        } else {
            out_o[ray * 3 + 0] = ox; out_o[ray * 3 + 1] = oy; out_o[ray * 3 + 2] = oz;
            out_d[ray * 3 + 0] = dx; out_d[ray * 3 + 1] = dy; out_d[ray * 3 + 2] = dz;
            refl_o[ray * 3 + 0] = ox; refl_o[ray * 3 + 1] = oy; refl_o[ray * 3 + 2] = oz;
            refl_d[ray * 3 + 0] = dx; refl_d[ray * 3 + 1] = dy; refl_d[ray * 3 + 2] = dz;
        }
        att_o[ray] = fin ? att1 : 0.f;
        fin_o[ray] = fin ? 1.f : 0.f;
        fp_o[ray * 3 + 0] = fpx; fp_o[ray * 3 + 1] = fpy; fp_o[ray * 3 + 2] = fpz;
        sp_o[ray * 3 + 0] = spx; sp_o[ray * 3 + 1] = spy; sp_o[ray * 3 + 2] = spz;
    }
}

__global__ void zero_counter_kernel() {
    g_ray_counter = 0;
}

__global__ void __launch_bounds__(NTH, 3)
trace_kernel(const float* __restrict__ go, const float* __restrict__ gd,
             const float* __restrict__ gW1, const float* __restrict__ gb1,
             const float* __restrict__ gW2, const float* __restrict__ gb2,
             const float* __restrict__ gW3, const float* __restrict__ gb3,
             float* __restrict__ out, int N) {
    __shared__ __align__(16) Shm s;
    int tid = threadIdx.x;
    for (int i = tid; i < 192; i += NTH) ((float*)s.W1)[i] = gW1[i];
    for (int i = tid; i < 64; i += NTH) {
        s.b1[i] = gb1[i];
        s.b2[i] = gb2[i];
        s.W3[i] = gW3[i];
    }
    if (tid == 0) s.b3 = gb3[0];
    for (int i = tid; i < 64 * 32; i += NTH) {
        int r = i >> 5, c = i & 31;
        s.W2p[r][c] = make_float2(gW2[r * 64 + c], gW2[r * 64 + c + 32]);
        s.W2q[r][c] = make_float2(gW2[c * 64 + r], gW2[(c + 32) * 64 + r]);
    }
    __syncthreads();

    int w = tid >> 5;
    const int lane = tid & 31;
    const int lane2 = lane + 32;

    LaneW lw;
    lw.w1xa = s.W1[0][lane]; lw.w1ya = s.W1[1][lane]; lw.w1za = s.W1[2][lane]; lw.b1a = s.b1[lane];
    lw.w1xb = s.W1[0][lane2]; lw.w1yb = s.W1[1][lane2]; lw.w1zb = s.W1[2][lane2]; lw.b1b = s.b1[lane2];
    lw.b2a = s.b2[lane]; lw.b2b = s.b2[lane2];
    lw.w3a = s.W3[lane]; lw.w3b = s.W3[lane2];
    lw.b3 = s.b3;

    // Persistent warp loop with dynamic ray fetch.
    for (;;) {
        int ray = 0;
        if (lane == 0) ray = atomicAdd(&g_ray_counter, 1);
        ray = __shfl_sync(FULLMASK, ray, 0);
        if (ray >= N) break;
        process_ray(s, w, lw, ray, go, gd, out, N);
    }
}

extern "C" void kernel_launch(void* const* d_in, const int* in_sizes, int n_in,
                              void* d_out, int out_size) {
    const float* o = (const float*)d_in[0];
    const float* d = (const float*)d_in[1];
    const float* W1 = (const float*)d_in[2];
    const float* b1 = (const float*)d_in[3];
    const float* W2 = (const float*)d_in[4];
    const float* b2 = (const float*)d_in[5];
    const float* W3 = (const float*)d_in[6];
    const float* b3 = (const float*)d_in[7];
    int N = in_sizes[0] / 3;

    zero_counter_kernel<<<1, 1>>>();

    // Persistent grid: 3 blocks/SM x 148 SMs.
    int blocks = 444;
    int max_blocks = (N + WPB - 1) / WPB;
    if (blocks > max_blocks) blocks = max_blocks;
    trace_kernel<<<blocks, NTH>>>(o, d, W1, b1, W2, b2, W3, b3, (float*)d_out, N);
}

// round 17
// speedup vs baseline: 1.3361x; 1.1535x over previous
#include <cuda_runtime.h>
#include <cuda_bf16.h>

#define FULLMASK 0xffffffffu
#define WPB 8
#define NTH (WPB * 32)

#define RADIUS_ 0.1f
#define TH_ 5e-5f
#define BMIN_ -0.15f
#define BMAX_ 0.15f
#define BIGT_ 1e10f

__device__ int g_ray_counter;

struct Shm {
    float buf[WPB][4][64];     // per-warp broadcast buffer (h1 / u), 16B-aligned
    float2 W2p[64][32];        // W2p[i][j] = (W2[i][j], W2[i][j+32])
    float2 W2q[64][32];        // W2q[j][i] = (W2[i][j], W2[i+32][j])
    float W1[3][64];
    float b1[64], b2[64], W3[64];
    float b3;
};

// Per-lane loop-invariant weights held in registers (hoisted out of sdf_eval).
struct LaneW {
    float w1xa, w1ya, w1za, b1a;
    float w1xb, w1yb, w1zb, b1b;
    float b2a, b2b, w3a, w3b, b3;
};

__device__ __forceinline__ float sp_(float x) {
    return fmaxf(x, 0.f) + __logf(1.f + __expf(-fabsf(x)));
}
__device__ __forceinline__ float sig_(float x) {
    return 1.f / (1.f + __expf(-x));
}
__device__ __forceinline__ float wsum(float v) {
    v += __shfl_xor_sync(FULLMASK, v, 16);
    v += __shfl_xor_sync(FULLMASK, v, 8);
    v += __shfl_xor_sync(FULLMASK, v, 4);
    v += __shfl_xor_sync(FULLMASK, v, 2);
    v += __shfl_xor_sync(FULLMASK, v, 1);
    return v;
}

// Warp-cooperative SDF eval of B points p = o + t[b]*d. All lanes get all B results.
template <int B>
__device__ __forceinline__ void sdf_eval(Shm& s, int w, const LaneW& lw,
                                         float ox, float oy, float oz,
                                         float dx, float dy, float dz,
                                         const float* t, float* outv) {
    const int lane = threadIdx.x & 31;
    float r[B];
    __syncwarp();
#pragma unroll
    for (int b = 0; b < B; b++) {
        float px = fmaf(t[b], dx, ox);
        float py = fmaf(t[b], dy, oy);
        float pz = fmaf(t[b], dz, oz);
        r[b] = sqrtf(fmaf(px, px, fmaf(py, py, pz * pz)) + 1e-12f);
        float za = fmaf(pz, lw.w1za, fmaf(py, lw.w1ya, fmaf(px, lw.w1xa, lw.b1a)));
        float zb = fmaf(pz, lw.w1zb, fmaf(py, lw.w1yb, fmaf(px, lw.w1xb, lw.b1b)));
        s.buf[w][b][lane] = sp_(za);
        s.buf[w][b][lane + 32] = sp_(zb);
    }
    __syncwarp();
    float za[B], zb[B];
#pragma unroll
    for (int b = 0; b < B; b++) { za[b] = lw.b2a; zb[b] = lw.b2b; }
#pragma unroll 2
    for (int i = 0; i < 64; i += 4) {
        float2 w0 = s.W2p[i + 0][lane];
        float2 w1 = s.W2p[i + 1][lane];
        float2 w2 = s.W2p[i + 2][lane];
        float2 w3 = s.W2p[i + 3][lane];
#pragma unroll
        for (int b = 0; b < B; b++) {
            float4 h = *(const float4*)&s.buf[w][b][i];
            za[b] = fmaf(h.x, w0.x, za[b]); zb[b] = fmaf(h.x, w0.y, zb[b]);
            za[b] = fmaf(h.y, w1.x, za[b]); zb[b] = fmaf(h.y, w1.y, zb[b]);
            za[b] = fmaf(h.z, w2.x, za[b]); zb[b] = fmaf(h.z, w2.y, zb[b]);
            za[b] = fmaf(h.w, w3.x, za[b]); zb[b] = fmaf(h.w, w3.y, zb[b]);
        }
    }
#pragma unroll
    for (int b = 0; b < B; b++) {
        float part = fmaf(sp_(za[b]), lw.w3a, sp_(zb[b]) * lw.w3b);
        float z3 = wsum(part) + lw.b3;
        float pert = tanhf(z3);
        outv[b] = r[b] - RADIUS_ + 0.01f * pert;
    }
}

// Analytic gradient of the SDF, normalized. All lanes get the normal.
__device__ __forceinline__ void sdf_normal(Shm& s, int w, const LaneW& lw,
                                           float px, float py, float pz, float* nrm) {
    const int lane = threadIdx.x & 31;
    float za = fmaf(pz, lw.w1za, fmaf(py, lw.w1ya, fmaf(px, lw.w1xa, lw.b1a)));
    float zb = fmaf(pz, lw.w1zb, fmaf(py, lw.w1yb, fmaf(px, lw.w1xb, lw.b1b)));
    float s1a = sig_(za), s1b = sig_(zb);
    __syncwarp();
    s.buf[w][0][lane] = sp_(za);
    s.buf[w][0][lane + 32] = sp_(zb);
    __syncwarp();
    float z2a = lw.b2a, z2b = lw.b2b;
#pragma unroll 2
    for (int i = 0; i < 64; i += 4) {
        float2 w0 = s.W2p[i + 0][lane];
        float2 w1 = s.W2p[i + 1][lane];
        float2 w2 = s.W2p[i + 2][lane];
        float2 w3 = s.W2p[i + 3][lane];
        float4 h = *(const float4*)&s.buf[w][0][i];
        z2a = fmaf(h.x, w0.x, z2a); z2b = fmaf(h.x, w0.y, z2b);
        z2a = fmaf(h.y, w1.x, z2a); z2b = fmaf(h.y, w1.y, z2b);
        z2a = fmaf(h.z, w2.x, z2a); z2b = fmaf(h.z, w2.y, z2b);
        z2a = fmaf(h.w, w3.x, z2a); z2b = fmaf(h.w, w3.y, z2b);
    }
    float part = fmaf(sp_(z2a), lw.w3a, sp_(z2b) * lw.w3b);
    float z3 = wsum(part) + lw.b3;
    float t = tanhf(z3);
    float ua = lw.w3a * sig_(z2a), ub = lw.w3b * sig_(z2b);
    __syncwarp();
    s.buf[w][0][lane] = ua;
    s.buf[w][0][lane + 32] = ub;
    __syncwarp();
    float sa = 0.f, sb = 0.f;
#pragma unroll 2
    for (int j = 0; j < 64; j += 4) {
        float2 q0 = s.W2q[j + 0][lane];
        float2 q1 = s.W2q[j + 1][lane];
        float2 q2 = s.W2q[j + 2][lane];
        float2 q3 = s.W2q[j + 3][lane];
        float4 u = *(const float4*)&s.buf[w][0][j];
        sa = fmaf(u.x, q0.x, sa); sb = fmaf(u.x, q0.y, sb);
        sa = fmaf(u.y, q1.x, sa); sb = fmaf(u.y, q1.y, sb);
        sa = fmaf(u.z, q2.x, sa); sb = fmaf(u.z, q2.y, sb);
        sa = fmaf(u.w, q3.x, sa); sb = fmaf(u.w, q3.y, sb);
    }
    float g1a = s1a * sa, g1b = s1b * sb;
    float gx = wsum(fmaf(lw.w1xa, g1a, lw.w1xb * g1b));
    float gy = wsum(fmaf(lw.w1ya, g1a, lw.w1yb * g1b));
    float gz = wsum(fmaf(lw.w1za, g1a, lw.w1zb * g1b));
    float coef = 0.01f * (1.f - t * t);
    float r = sqrtf(fmaf(px, px, fmaf(py, py, pz * pz)) + 1e-12f);
    float invr = 1.f / r;
    float Gx = fmaf(coef, gx, px * invr);
    float Gy = fmaf(coef, gy, py * invr);
    float Gz = fmaf(coef, gz, pz * invr);
    float nn = sqrtf(Gx * Gx + Gy * Gy + Gz * Gz) + 1e-12f;
    float inv = 1.f / nn;
    nrm[0] = Gx * inv; nrm[1] = Gy * inv; nrm[2] = Gz * inv;
}

__device__ __forceinline__ void aabb(float ox, float oy, float oz,
                                     float dx, float dy, float dz,
                                     float& t_near, float& t_far, bool& hit) {
    float ddx = (fabsf(dx) < 1e-9f) ? 1e-9f : dx;
    float ddy = (fabsf(dy) < 1e-9f) ? 1e-9f : dy;
    float ddz = (fabsf(dz) < 1e-9f) ? 1e-9f : dz;
    float ix = 1.f / ddx, iy = 1.f / ddy, iz = 1.f / ddz;
    float t1x = (BMIN_ - ox) * ix, t2x = (BMAX_ - ox) * ix;
    float t1y = (BMIN_ - oy) * iy, t2y = (BMAX_ - oy) * iy;
    float t1z = (BMIN_ - oz) * iz, t2z = (BMAX_ - oz) * iz;
    float tmin = fmaxf(fmaxf(fminf(t1x, t2x), fminf(t1y, t2y)), fminf(t1z, t2z));
    float tmax = fminf(fminf(fmaxf(t1x, t2x), fmaxf(t1y, t2y)), fmaxf(t1z, t2z));
    hit = (tmax >= tmin) && (tmax > 0.f);
    t_near = hit ? fmaxf(tmin, 0.f) : BIGT_;
    t_far = hit ? tmax : BIGT_;
}

__device__ __forceinline__ void refract(float lx, float ly, float lz,
                                        float nx, float ny, float nz,
                                        float eta1, float eta2,
                                        float* t, float& att) {
    float ct = -(lx * nx + ly * ny + lz * nz);
    float ipx = fmaf(nx, ct, lx);
    float ipy = fmaf(ny, ct, ly);
    float ipz = fmaf(nz, ct, lz);
    float k = eta1 / eta2;
    float tpx = k * ipx, tpy = k * ipy, tpz = k * ipz;
    float tpn = tpx * tpx + tpy * tpy + tpz * tpz;
    float c = fminf(fmaxf(tpn, 0.f), 0.999999f);
    float ti = sqrtf(1.f - c);
    float tx = fmaf(-nx, ti, tpx);
    float ty = fmaf(-ny, ti, tpy);
    float tz = fmaf(-nz, ti, tpz);
    float nn = sqrtf(tx * tx + ty * ty + tz * tz) + 1e-10f;
    float inv = 1.f / nn;
    tx *= inv; ty *= inv; tz *= inv;
    float ctt = -(tx * nx + ty * ny + tz * nz);
    float ei = (ctt * eta1 - ct * eta2) / (ctt * eta1 + ct * eta2 + 1e-10f);
    float ep = (ctt * eta2 - ct * eta1) / (ctt * eta2 + ct * eta1 + 1e-10f);
    att = fminf(fmaxf(0.5f * (ei * ei + ep * ep), 0.f), 1.f);
    t[0] = tx; t[1] = ty; t[2] = tz;
}

__device__ __forceinline__ void reflect(float lx, float ly, float lz,
                                        const float* n, float* r) {
    float dn = lx * n[0] + ly * n[1] + lz * n[2];
    float rx = fmaf(-2.f * dn, n[0], lx);
    float ry = fmaf(-2.f * dn, n[1], ly);
    float rz = fmaf(-2.f * dn, n[2], lz);
    float nn = sqrtf(rx * rx + ry * ry + rz * rz) + 1e-10f;
    float inv = 1.f / nn;
    r[0] = rx * inv; r[1] = ry * inv; r[2] = rz * inv;
}

__device__ __forceinline__ void intersect_sdf(Shm& s, int w, const LaneW& lw,
                                              float ox, float oy, float oz,
                                              float dx, float dy, float dz,
                                              bool mask, float t_near, float t_far, bool far_,
                                              bool& valid, float& depth, float* nrm) {
    float acc_s = mask ? t_near : 0.f;
    float acc_e = mask ? t_far : 0.f;
    bool unf_s = false, unf_e = false;
    float cs = 0.f, ce = 0.f;   // invariant: cs = sdf(acc_s), ce = sdf(acc_e) when flag alive
    if (mask) {
        float t[2] = {acc_s, acc_e};
        float v[2];
        sdf_eval<2>(s, w, lw, ox, oy, oz, dx, dy, dz, t, v);
        cs = v[0]; ce = v[1];
        unf_s = fabsf(cs) > TH_;
        unf_e = fabsf(ce) > TH_;
    }
#pragma unroll 1
    for (int it = 0; it < 15; ++it) {
        if (!(unf_s || unf_e)) break;
        // cs/ce already hold sdf at current acc_s/acc_e (reference evaluates here).
        if (unf_s) acc_s += cs;
        if (unf_e) acc_e -= ce;
        bool nc = acc_s < acc_e;
        unf_s = unf_s && (fabsf(cs) > TH_) && nc;
        unf_e = unf_e && (fabsf(ce) > TH_) && nc;
        if ((unf_s || unf_e) && it < 14) {
            // evaluate at the new positions for the next iteration
            if (unf_s && unf_e) {
                float t[2] = {acc_s, acc_e};
                float v[2];
                sdf_eval<2>(s, w, lw, ox, oy, oz, dx, dy, dz, t, v);
                cs = v[0]; ce = v[1];
            } else if (unf_s) {
                sdf_eval<1>(s, w, lw, ox, oy, oz, dx, dy, dz, &acc_s, &cs);
            } else {
                sdf_eval<1>(s, w, lw, ox, oy, oz, dx, dy, dz, &acc_e, &ce);
            }
        }
    }
    bool net = acc_s < acc_e;
    bool smask = far_ ? unf_e : unf_s;
    if (smask) {
        const int lane = threadIdx.x & 31;
        float dt = acc_e - acc_s;
        float vlo = 0.f, vhi = 0.f;
        // Directional early-exit sampler (exact):
        //  - near pass needs the FIRST negative -> ascending scan, stop at first
        //    block containing a negative (later samples cannot change argmax).
        //  - far pass needs the LAST negative -> descending scan, stop at first
        //    block (from top) containing a negative (lower-index negatives
        //    cannot change last_neg). Unevaluated entries stay 0.0f (not
        //    negative) so the ballots below are unaffected.
        {
            bool found = false;
            int base = far_ ? 60 : 0;
#pragma unroll 1
            for (int blk = 0; blk < 16 && !found; ++blk) {
                float t[4], v[4];
#pragma unroll
                for (int j = 0; j < 4; j++)
                    t[j] = fmaf((float)(base + j) * (1.f / 63.f), dt, acc_s);
                sdf_eval<4>(s, w, lw, ox, oy, oz, dx, dy, dz, t, v);
#pragma unroll
                for (int j = 0; j < 4; j++) {
                    int k = base + j;
                    if (lane == k) vlo = v[j];
                    if (lane == k - 32) vhi = v[j];
                }
                // v[] is warp-uniform -> 'found' is warp-uniform (no divergence)
                found = (v[0] < 0.f) || (v[1] < 0.f) || (v[2] < 0.f) || (v[3] < 0.f);
                base += far_ ? -4 : 4;
            }
        }
        unsigned mlo = __ballot_sync(FULLMASK, vlo < 0.f);
        unsigned mhi = __ballot_sync(FULLMASK, vhi < 0.f);
        unsigned long long m = (((unsigned long long)mhi) << 32) | (unsigned long long)mlo;
        bool any = (m != 0ull);
        int ia, ib;
        bool has;
        if (!far_) {
            int idx = any ? (__ffsll((long long)m) - 1) : 0;
            has = any && (idx > 0);
            ia = (idx > 0) ? idx - 1 : 0;
            ib = idx;
        } else {
            int ln = any ? (63 - __clzll((long long)m)) : 63;
            has = any && (ln < 63);
            ia = ln;
            ib = (ln + 1 > 63) ? 63 : ln + 1;
        }
        float f_a = (ia < 32) ? __shfl_sync(FULLMASK, vlo, ia) : __shfl_sync(FULLMASK, vhi, ia - 32);
        float f_b = (ib < 32) ? __shfl_sync(FULLMASK, vlo, ib) : __shfl_sync(FULLMASK, vhi, ib - 32);
        float t_a = fmaf((float)ia * (1.f / 63.f), dt, acc_s);
        float t_b = fmaf((float)ib * (1.f / 63.f), dt, acc_s);
#pragma unroll 1
        for (int it = 0; it < 8; ++it) {
            // Converged bracket: further iterations change depth by < 1e-7.
            if (fabsf(t_b - t_a) < 1e-7f) break;
            float den = f_b - f_a;
            if (fabsf(den) < 1e-12f) den = 1e-12f;
            float t_mid = t_a - f_a * (t_b - t_a) / den;
            float fm;
            sdf_eval<1>(s, w, lw, ox, oy, oz, dx, dy, dz, &t_mid, &fm);
            bool same = (fm > 0.f) == (f_a > 0.f);
            if (same) { t_a = t_mid; f_a = fm; }
            else      { t_b = t_mid; f_b = fm; }
        }
        float den = f_b - f_a;
        if (fabsf(den) < 1e-12f) den = 1e-12f;
        depth = t_a - f_a * (t_b - t_a) / den;
        net = has;
    } else {
        depth = far_ ? acc_e : acc_s;
    }
    valid = net && mask;
    nrm[0] = 0.f; nrm[1] = 0.f; nrm[2] = 0.f;
    if (valid) {
        sdf_normal(s, w, lw, fmaf(depth, dx, ox), fmaf(depth, dy, oy), fmaf(depth, dz, oz), nrm);
    }
}

__device__ __forceinline__ void process_ray(Shm& s, int w, const LaneW& lw, int ray,
                                            const float* __restrict__ go,
                                            const float* __restrict__ gd,
                                            float* __restrict__ out, int N) {
    int tid = threadIdx.x;
    float ox = go[ray * 3 + 0], oy = go[ray * 3 + 1], oz = go[ray * 3 + 2];
    float dx = gd[ray * 3 + 0], dy = gd[ray * 3 + 1], dz = gd[ray * 3 + 2];

    float tn, tf;
    bool hit;
    aabb(ox, oy, oz, dx, dy, dz, tn, tf, hit);

    bool valid;
    float depth1;
    float n1[3];
    intersect_sdf(s, w, lw, ox, oy, oz, dx, dy, dz, hit, tn, tf, false, valid, depth1, n1);

    float fpx = fmaf(depth1, dx, ox);
    float fpy = fmaf(depth1, dy, oy);
    float fpz = fmaf(depth1, dz, oz);
    bool inside = (fpx >= BMIN_) && (fpx <= BMAX_) &&
                  (fpy >= BMIN_) && (fpy <= BMAX_) &&
                  (fpz >= BMIN_) && (fpz <= BMAX_);

    float lt1[3], att1;
    refract(dx, dy, dz, n1[0], n1[1], n1[2], 1.0003f, 1.45f, lt1, att1);
    float lr1[3];
    reflect(dx, dy, dz, n1, lr1);

    float o2x = fpx - lt1[0], o2y = fpy - lt1[1], o2z = fpz - lt1[2];
    float d2x = lt1[0], d2y = lt1[1], d2z = lt1[2];

    float tn2, tf2;
    bool hit2;
    aabb(o2x, o2y, o2z, d2x, d2y, d2z, tn2, tf2, hit2);
    bool mask2 = hit2 && inside && valid;

    bool valid2;
    float depth2;
    float n2[3];
    intersect_sdf(s, w, lw, o2x, o2y, o2z, d2x, d2y, d2z, mask2, tn2, tf2, true, valid2, depth2, n2);

    float spx = fmaf(depth2, d2x, o2x);
    float spy = fmaf(depth2, d2y, o2y);
    float spz = fmaf(depth2, d2z, o2z);

    float lt2[3], att2_unused;
    refract(d2x, d2y, d2z, -n2[0], -n2[1], -n2[2], 1.45f, 1.0003f, lt2, att2_unused);

    bool fin = valid && valid2;

    if ((tid & 31) == 0) {
        float* out_o = out;
        float* out_d = out + 3 * N;
        float* refl_o = out + 6 * N;
        float* refl_d = out + 9 * N;
        float* att_o = out + 12 * N;
        float* fin_o = out + 13 * N;
        float* fp_o = out + 14 * N;
        float* sp_o = out + 17 * N;

        if (fin) {
            out_o[ray * 3 + 0] = fmaf(0.1f, lt2[0], spx);
            out_o[ray * 3 + 1] = fmaf(0.1f, lt2[1], spy);
            out_o[ray * 3 + 2] = fmaf(0.1f, lt2[2], spz);
            out_d[ray * 3 + 0] = lt2[0];
            out_d[ray * 3 + 1] = lt2[1];
            out_d[ray * 3 + 2] = lt2[2];
            refl_o[ray * 3 + 0] = fmaf(0.1f, lr1[0], fpx);
            refl_o[ray * 3 + 1] = fmaf(0.1f, lr1[1], fpy);
            refl_o[ray * 3 + 2] = fmaf(0.1f, lr1[2], fpz);
            refl_d[ray * 3 + 0] = lr1[0];
            refl_d[ray * 3 + 1] = lr1[1];
            refl_d[ray * 3 + 2] = lr1[2];
        } else {
            out_o[ray * 3 + 0] = ox; out_o[ray * 3 + 1] = oy; out_o[ray * 3 + 2] = oz;
            out_d[ray * 3 + 0] = dx; out_d[ray * 3 + 1] = dy; out_d[ray * 3 + 2] = dz;
            refl_o[ray * 3 + 0] = ox; refl_o[ray * 3 + 1] = oy; refl_o[ray * 3 + 2] = oz;
            refl_d[ray * 3 + 0] = dx; refl_d[ray * 3 + 1] = dy; refl_d[ray * 3 + 2] = dz;
        }
        att_o[ray] = fin ? att1 : 0.f;
        fin_o[ray] = fin ? 1.f : 0.f;
        fp_o[ray * 3 + 0] = fpx; fp_o[ray * 3 + 1] = fpy; fp_o[ray * 3 + 2] = fpz;
        sp_o[ray * 3 + 0] = spx; sp_o[ray * 3 + 1] = spy; sp_o[ray * 3 + 2] = spz;
    }
}

__global__ void zero_counter_kernel() {
    g_ray_counter = 0;
}

__global__ void __launch_bounds__(NTH, 3)
trace_kernel(const float* __restrict__ go, const float* __restrict__ gd,
             const float* __restrict__ gW1, const float* __restrict__ gb1,
             const float* __restrict__ gW2, const float* __restrict__ gb2,
             const float* __restrict__ gW3, const float* __restrict__ gb3,
             float* __restrict__ out, int N) {
    __shared__ __align__(16) Shm s;
    int tid = threadIdx.x;
    for (int i = tid; i < 192; i += NTH) ((float*)s.W1)[i] = gW1[i];
    for (int i = tid; i < 64; i += NTH) {
        s.b1[i] = gb1[i];
        s.b2[i] = gb2[i];
        s.W3[i] = gW3[i];
    }
    if (tid == 0) s.b3 = gb3[0];
    for (int i = tid; i < 64 * 32; i += NTH) {
        int r = i >> 5, c = i & 31;
        s.W2p[r][c] = make_float2(gW2[r * 64 + c], gW2[r * 64 + c + 32]);
        s.W2q[r][c] = make_float2(gW2[c * 64 + r], gW2[(c + 32) * 64 + r]);
    }
    __syncthreads();

    int w = tid >> 5;
    const int lane = tid & 31;
    const int lane2 = lane + 32;

    LaneW lw;
    lw.w1xa = s.W1[0][lane]; lw.w1ya = s.W1[1][lane]; lw.w1za = s.W1[2][lane]; lw.b1a = s.b1[lane];
    lw.w1xb = s.W1[0][lane2]; lw.w1yb = s.W1[1][lane2]; lw.w1zb = s.W1[2][lane2]; lw.b1b = s.b1[lane2];
    lw.b2a = s.b2[lane]; lw.b2b = s.b2[lane2];
    lw.w3a = s.W3[lane]; lw.w3b = s.W3[lane2];
    lw.b3 = s.b3;

    // Persistent warp loop with dynamic ray fetch.
    for (;;) {
        int ray = 0;
        if (lane == 0) ray = atomicAdd(&g_ray_counter, 1);
        ray = __shfl_sync(FULLMASK, ray, 0);
        if (ray >= N) break;
        process_ray(s, w, lw, ray, go, gd, out, N);
    }
}

extern "C" void kernel_launch(void* const* d_in, const int* in_sizes, int n_in,
                              void* d_out, int out_size) {
    const float* o = (const float*)d_in[0];
    const float* d = (const float*)d_in[1];
    const float* W1 = (const float*)d_in[2];
    const float* b1 = (const float*)d_in[3];
    const float* W2 = (const float*)d_in[4];
    const float* b2 = (const float*)d_in[5];
    const float* W3 = (const float*)d_in[6];
    const float* b3 = (const float*)d_in[7];
    int N = in_sizes[0] / 3;

    zero_counter_kernel<<<1, 1>>>();

    // Persistent grid: 3 blocks/SM x 148 SMs.
    int blocks = 444;
    int max_blocks = (N + WPB - 1) / WPB;
    if (blocks > max_blocks) blocks = max_blocks;
    trace_kernel<<<blocks, NTH>>>(o, d, W1, b1, W2, b2, W3, b3, (float*)d_out, N);
}